// round 17
// baseline (speedup 1.0000x reference)
#include <cuda_runtime.h>
#include <math.h>
#include <stdint.h>

// Problem constants
#define NB     8
#define TT     64
#define JJ     25
#define CC     256       // D_MODEL
#define DI     512       // D_INNER
#define DS     16        // D_STATE
#define DTR    16        // DT_RANK
#define BTOT   (NB*JJ)   // 200
#define NROWS  (BTOT*TT) // 12800
#define XELEMS (NB*TT*JJ*CC)   // 13,107,200
#define WELEMS (2*DI*CC)       // 262,144

// ---------------- scratch ----------------
__device__ float    g_xc [NROWS * DI];
__device__ float    g_xc2[NROWS * DI];
__device__ float    g_z  [NROWS * DI];
__device__ float    g_dt [NROWS * DI];
__device__ float    g_y  [NROWS * DI];
__device__ float    g_Bm [NROWS * DS];
__device__ float    g_Cm [NROWS * DS];
__device__ uint32_t g_xt [XELEMS];     // x pre-converted to tf32 bits
__device__ uint32_t g_wt [WELEMS];     // W_in pre-converted to tf32 bits

// ---------------- helpers ----------------
__device__ __forceinline__ float silu_f(float v) { return v / (1.0f + __expf(-v)); }
__device__ __forceinline__ float softplus_f(float v) {
    return fmaxf(v, 0.0f) + log1pf(__expf(-fabsf(v)));
}
__device__ __forceinline__ uint32_t f2t(float f) {
    uint32_t u; asm("cvt.rna.tf32.f32 %0, %1;" : "=r"(u) : "f"(f)); return u;
}
__device__ __forceinline__ void mma8(float* c, uint32_t a0, uint32_t a1, uint32_t a2,
                                     uint32_t a3, uint32_t b0, uint32_t b1) {
    asm volatile(
        "mma.sync.aligned.m16n8k8.row.col.f32.tf32.tf32.f32 "
        "{%0,%1,%2,%3},{%4,%5,%6,%7},{%8,%9},{%0,%1,%2,%3};"
        : "+f"(c[0]), "+f"(c[1]), "+f"(c[2]), "+f"(c[3])
        : "r"(a0), "r"(a1), "r"(a2), "r"(a3), "r"(b0), "r"(b1));
}
__device__ __forceinline__ uint32_t smem_u32(const void* p) {
    uint32_t a;
    asm("{ .reg .u64 t; cvta.to.shared.u64 t, %1; cvt.u32.u64 %0, t; }" : "=r"(a) : "l"(p));
    return a;
}
__device__ __forceinline__ void cp16(uint32_t dst_smem, const void* src) {
    asm volatile("cp.async.cg.shared.global [%0], [%1], 16;" :: "r"(dst_smem), "l"(src));
}

// ---------------- k0: one-time tf32 pre-conversion ----------------
__global__ void k0_cvt(const float4* __restrict__ in, uint4* __restrict__ out, int n4) {
    int i = blockIdx.x * blockDim.x + threadIdx.x;
    if (i < n4) {
        float4 v = in[i];
        out[i] = make_uint4(f2t(v.x), f2t(v.y), f2t(v.z), f2t(v.w));
    }
}

// ---------------- k1: in-proj GEMM (tf32 mma, cp.async double-buffered) ----------
// Same tiling / fragment indexing / epilogue as the measured-good R3 kernel.
// Data path: pre-converted tf32 tiles pulled with cp.async into 2-stage smem.
__global__ __launch_bounds__(256) void k1_gemm_in() {
    extern __shared__ uint32_t smem[];           // 2*64*36 + 2*128*36 u32 = 55296 B
    uint32_t* sA = smem;                         // [2][64][36]
    uint32_t* sB = smem + 2 * 64 * 36;           // [2][128][36]
    const uint32_t sA_base = smem_u32(sA);
    const uint32_t sB_base = smem_u32(sB);

    const int tid = threadIdx.x, lane = tid & 31, warp = tid >> 5;
    const int lr = lane >> 2, lk = lane & 3;
    const int b = blockIdx.x, n0 = blockIdx.y * 128;
    const int n = b / 25, j = b - n * 25;
    const uint32_t* xbase = g_xt + ((size_t)(n * TT) * JJ + j) * CC;
    const int wr = (warp >> 2) * 32, wc = (warp & 3) * 32;

    float acc[2][4][4];
    #pragma unroll
    for (int i = 0; i < 2; i++)
        #pragma unroll
        for (int jj = 0; jj < 4; jj++)
            #pragma unroll
            for (int q = 0; q < 4; q++) acc[i][jj][q] = 0.0f;

    const int ar = tid >> 2, ac = (tid & 3) * 8;
    const int br = tid >> 1, bc = (tid & 1) * 16;

    auto prefetch = [&](int stage, int c0) {
        // A: 2x16B per thread
        uint32_t da = sA_base + ((stage * 64 + ar) * 36 + ac) * 4;
        const uint32_t* pa = xbase + (size_t)ar * JJ * CC + c0 + ac;
        cp16(da,      pa);
        cp16(da + 16, pa + 4);
        // B: 4x16B per thread
        uint32_t db = sB_base + ((stage * 128 + br) * 36 + bc) * 4;
        const uint32_t* pb = g_wt + (size_t)(n0 + br) * CC + c0 + bc;
        #pragma unroll
        for (int q = 0; q < 4; q++) cp16(db + 16 * q, pb + 4 * q);
        asm volatile("cp.async.commit_group;");
    };

    prefetch(0, 0);
    #pragma unroll 1
    for (int i = 0; i < 8; i++) {
        const int c0 = i * 32;
        if (i + 1 < 8) {
            prefetch((i + 1) & 1, c0 + 32);
            asm volatile("cp.async.wait_group 1;");
        } else {
            asm volatile("cp.async.wait_group 0;");
        }
        __syncthreads();
        const int st = i & 1;
        const uint32_t* cA = sA + (size_t)st * 64 * 36;
        const uint32_t* cB = sB + (size_t)st * 128 * 36;
        #pragma unroll
        for (int kk = 0; kk < 4; kk++) {
            const int k0 = kk * 8;
            uint32_t a[2][4], bb[4][2];
            #pragma unroll
            for (int ii = 0; ii < 2; ii++) {
                a[ii][0] = cA[(wr+16*ii+lr  ) * 36 + k0+lk];
                a[ii][1] = cA[(wr+16*ii+8+lr) * 36 + k0+lk];
                a[ii][2] = cA[(wr+16*ii+lr  ) * 36 + k0+lk+4];
                a[ii][3] = cA[(wr+16*ii+8+lr) * 36 + k0+lk+4];
            }
            #pragma unroll
            for (int jj = 0; jj < 4; jj++) {
                bb[jj][0] = cB[(wc+8*jj+lr) * 36 + k0+lk];
                bb[jj][1] = cB[(wc+8*jj+lr) * 36 + k0+lk+4];
            }
            #pragma unroll
            for (int ii = 0; ii < 2; ii++)
                #pragma unroll
                for (int jj = 0; jj < 4; jj++)
                    mma8(acc[ii][jj], a[ii][0], a[ii][1], a[ii][2], a[ii][3], bb[jj][0], bb[jj][1]);
        }
        __syncthreads();
    }

    float* dst; int eoff;
    if (n0 < DI) { dst = g_xc; eoff = n0; } else { dst = g_z; eoff = n0 - DI; }
    #pragma unroll
    for (int i = 0; i < 2; i++) {
        const int r0 = wr + 16*i + lr, r1 = r0 + 8;
        const size_t m0r = (size_t)(b * TT + r0) * DI;
        const size_t m1r = (size_t)(b * TT + r1) * DI;
        #pragma unroll
        for (int jj = 0; jj < 4; jj++) {
            const int col = eoff + wc + 8*jj + 2*lk;
            *(float2*)&dst[m0r + col] = make_float2(acc[i][jj][0], acc[i][jj][1]);
            *(float2*)&dst[m1r + col] = make_float2(acc[i][jj][2], acc[i][jj][3]);
        }
    }
}

// ---------------- k2: depthwise causal conv + bias + SiLU — verbatim ----
__global__ void k2_conv(const float* __restrict__ conv_w,
                        const float* __restrict__ conv_b) {
    int idx = blockIdx.x * blockDim.x + threadIdx.x;
    if (idx >= NROWS * DI) return;
    int d = idx & (DI - 1);
    int m = idx >> 9;
    int t = m & 63;
    float s = conv_b[d];
    #pragma unroll
    for (int k = 0; k < 4; k++) {
        int tt = t - 3 + k;
        if (tt >= 0) s = fmaf(conv_w[d * 4 + k], g_xc[(size_t)(m - 3 + k) * DI + d], s);
    }
    g_xc2[idx] = silu_f(s);
}

// ---------------- k3: x_dbl projection + dt projection (float4 smem) — verbatim ----
__global__ __launch_bounds__(256) void k3_xproj(const float* __restrict__ Wx,
                                                const float* __restrict__ Wdt,
                                                const float* __restrict__ bdt) {
    __shared__ __align__(16) float buf[13568];
    float* sX = buf;                      // [64][68]
    float* sW = buf + 64 * 68;            // [48][68]
    const int tid = threadIdx.x;
    const int m0 = blockIdx.x * 64;
    const int row = tid >> 2, c0 = (tid & 3) * 12;

    float acc[12];
    #pragma unroll
    for (int i = 0; i < 12; i++) acc[i] = 0.0f;

    for (int k0 = 0; k0 < DI; k0 += 64) {
        __syncthreads();
        for (int idx = tid; idx < 64 * 16; idx += 256) {
            int r = idx >> 4, q = idx & 15;
            *(float4*)&sX[r * 68 + q * 4] =
                *(const float4*)&g_xc2[(size_t)(m0 + r) * DI + k0 + q * 4];
        }
        for (int idx = tid; idx < 48 * 16; idx += 256) {
            int r = idx >> 4, q = idx & 15;
            *(float4*)&sW[r * 68 + q * 4] =
                *(const float4*)&Wx[(size_t)r * DI + k0 + q * 4];
        }
        __syncthreads();
        #pragma unroll 4
        for (int q = 0; q < 16; q++) {
            float4 xv = *(const float4*)&sX[row * 68 + q * 4];
            #pragma unroll
            for (int i = 0; i < 12; i++) {
                float4 wv = *(const float4*)&sW[(c0 + i) * 68 + q * 4];
                acc[i] = fmaf(xv.x, wv.x, acc[i]);
                acc[i] = fmaf(xv.y, wv.y, acc[i]);
                acc[i] = fmaf(xv.z, wv.z, acc[i]);
                acc[i] = fmaf(xv.w, wv.w, acc[i]);
            }
        }
    }
    __syncthreads();

    float* sD   = buf;                    // [64][52]
    float* sWdt = buf + 64 * 52;          // [512][20]
    #pragma unroll
    for (int i = 0; i < 12; i++) sD[row * 52 + c0 + i] = acc[i];
    for (int idx = tid; idx < 512 * 4; idx += 256) {
        int d = idx >> 2, q = idx & 3;
        *(float4*)&sWdt[d * 20 + q * 4] = *(const float4*)&Wdt[d * 16 + q * 4];
    }
    __syncthreads();

    for (int idx = tid; idx < 64 * 32; idx += 256) {
        int r = idx >> 5, v = idx & 31;
        float val = sD[r * 52 + DTR + v];
        if (v < 16) g_Bm[(size_t)(m0 + r) * DS + v]        = val;
        else        g_Cm[(size_t)(m0 + r) * DS + (v - 16)] = val;
    }
    for (int idx = tid; idx < 64 * DI; idx += 256) {
        int r = idx >> 9, d = idx & 511;
        float a = bdt[d];
        #pragma unroll
        for (int q = 0; q < 4; q++) {
            float4 dv = *(const float4*)&sD[r * 52 + q * 4];
            float4 wv = *(const float4*)&sWdt[d * 20 + q * 4];
            a = fmaf(dv.x, wv.x, a);
            a = fmaf(dv.y, wv.y, a);
            a = fmaf(dv.z, wv.z, a);
            a = fmaf(dv.w, wv.w, a);
        }
        g_dt[(size_t)(m0 + r) * DI + d] = softplus_f(a);
    }
}

// ---------------- k4: selective scan — R10 version verbatim -------
__global__ __launch_bounds__(128) void k4_scan(const float* __restrict__ A_log,
                                               const float* __restrict__ D_skip) {
    const int tid = threadIdx.x;
    const int b   = blockIdx.x;
    const int d   = blockIdx.y * 128 + tid;

    float Aa[DS], h[DS];
    bool fast = true;
    #pragma unroll
    for (int s = 0; s < DS; s++) {
        Aa[s] = -__expf(A_log[d * DS + s]);
        fast = fast && (fabsf(Aa[s] + (float)(s + 1)) < 1e-4f * (float)(s + 1));
        h[s] = 0.0f;
    }
    const float Dk = D_skip[d];

    const size_t rowbase = (size_t)b * TT * DI + d;
    const float* pdt = g_dt  + rowbase;
    const float* pxc = g_xc2 + rowbase;
    const float* pz  = g_z   + rowbase;
    float*       py  = g_y   + rowbase;
    const float4* pB = (const float4*)(g_Bm + (size_t)b * TT * DS);
    const float4* pC = (const float4*)(g_Cm + (size_t)b * TT * DS);

    if (fast) {
        for (int t = 0; t < TT; t++) {
            const size_t o = (size_t)t * DI;
            float dt = pdt[o], xc = pxc[o], z = pz[o];
            float Bv[DS], Cv[DS];
            #pragma unroll
            for (int q = 0; q < 4; q++) {
                float4 bq = pB[t*4 + q], cq = pC[t*4 + q];
                Bv[4*q]=bq.x; Bv[4*q+1]=bq.y; Bv[4*q+2]=bq.z; Bv[4*q+3]=bq.w;
                Cv[4*q]=cq.x; Cv[4*q+1]=cq.y; Cv[4*q+2]=cq.z; Cv[4*q+3]=cq.w;
            }
            const float du = dt * xc;
            const float w = __expf(-dt);
            float pw = w, y = 0.0f;
            #pragma unroll
            for (int s = 0; s < DS; s++) {
                h[s] = fmaf(pw, h[s], du * Bv[s]);
                y    = fmaf(h[s], Cv[s], y);
                pw  *= w;
            }
            y = fmaf(xc, Dk, y);
            py[o] = y * silu_f(z);
        }
    } else {
        for (int t = 0; t < TT; t++) {
            const size_t o = (size_t)t * DI;
            float dt = pdt[o], xc = pxc[o], z = pz[o];
            float Bv[DS], Cv[DS];
            #pragma unroll
            for (int q = 0; q < 4; q++) {
                float4 bq = pB[t*4 + q], cq = pC[t*4 + q];
                Bv[4*q]=bq.x; Bv[4*q+1]=bq.y; Bv[4*q+2]=bq.z; Bv[4*q+3]=bq.w;
                Cv[4*q]=cq.x; Cv[4*q+1]=cq.y; Cv[4*q+2]=cq.z; Cv[4*q+3]=cq.w;
            }
            const float du = dt * xc;
            float y = 0.0f;
            #pragma unroll
            for (int s = 0; s < DS; s++) {
                float dA = __expf(dt * Aa[s]);
                h[s] = fmaf(dA, h[s], du * Bv[s]);
                y    = fmaf(h[s], Cv[s], y);
            }
            y = fmaf(xc, Dk, y);
            py[o] = y * silu_f(z);
        }
    }
}

// ---------------- k5: out-proj GEMM (tf32, pair-major smem) — R15 verbatim ----
__global__ __launch_bounds__(256) void k5_gemm_out(const float* __restrict__ x,
                                                   const float* __restrict__ W,
                                                   const float* __restrict__ ln_w,
                                                   float* __restrict__ out) {
    __shared__ uint2 sA2[16 * 36];
    __shared__ uint2 sB2[16 * 260];
    __shared__ float rowsq[32];
    const int tid = threadIdx.x, lane = tid & 31, warp = tid >> 5;
    const int lr = lane >> 2, lk = lane & 3;
    const int m0 = blockIdx.x * 32;
    const int wr = (warp >> 2) * 16, wc = (warp & 3) * 64;

    if (tid < 32) rowsq[tid] = 0.0f;

    float acc[8][4];
    #pragma unroll
    for (int jj = 0; jj < 8; jj++)
        #pragma unroll
        for (int q = 0; q < 4; q++) acc[jj][q] = 0.0f;

    const int ar = tid >> 3, aq = tid & 7;
    const int akk = aq >> 1, aoff = (aq & 1) * 2;
    const int br = tid;

    for (int d0 = 0; d0 < DI; d0 += 32) {
        __syncthreads();
        {
            const float* yrow = &g_y[(size_t)(m0 + ar) * DI + d0 + akk * 8 + aoff];
            float2 lo = *(const float2*)(yrow);
            float2 hi = *(const float2*)(yrow + 4);
            sA2[(akk * 4 + aoff    ) * 36 + ar] = make_uint2(f2t(lo.x), f2t(hi.x));
            sA2[(akk * 4 + aoff + 1) * 36 + ar] = make_uint2(f2t(lo.y), f2t(hi.y));
        }
        {
            const float4* p = (const float4*)(W + (size_t)br * DI + d0);
            #pragma unroll
            for (int kk = 0; kk < 4; kk++) {
                float4 v0 = p[2*kk], v1 = p[2*kk + 1];
                sB2[(kk * 4 + 0) * 260 + br] = make_uint2(f2t(v0.x), f2t(v1.x));
                sB2[(kk * 4 + 1) * 260 + br] = make_uint2(f2t(v0.y), f2t(v1.y));
                sB2[(kk * 4 + 2) * 260 + br] = make_uint2(f2t(v0.z), f2t(v1.z));
                sB2[(kk * 4 + 3) * 260 + br] = make_uint2(f2t(v0.w), f2t(v1.w));
            }
        }
        __syncthreads();
        #pragma unroll
        for (int kk = 0; kk < 4; kk++) {
            const int pidx = kk * 4 + lk;
            uint2 av0 = sA2[pidx * 36 + wr + lr];
            uint2 av1 = sA2[pidx * 36 + wr + 8 + lr];
            #pragma unroll
            for (int jj = 0; jj < 8; jj++) {
                uint2 bv = sB2[pidx * 260 + wc + 8*jj + lr];
                mma8(acc[jj], av0.x, av1.x, av0.y, av1.y, bv.x, bv.y);
            }
        }
    }

    float s0 = 0.0f, s1 = 0.0f;
    #pragma unroll
    for (int jj = 0; jj < 8; jj++) {
        s0 += acc[jj][0]*acc[jj][0] + acc[jj][1]*acc[jj][1];
        s1 += acc[jj][2]*acc[jj][2] + acc[jj][3]*acc[jj][3];
    }
    s0 += __shfl_xor_sync(0xffffffffu, s0, 1); s0 += __shfl_xor_sync(0xffffffffu, s0, 2);
    s1 += __shfl_xor_sync(0xffffffffu, s1, 1); s1 += __shfl_xor_sync(0xffffffffu, s1, 2);
    if (lk == 0) { atomicAdd(&rowsq[wr + lr], s0); atomicAdd(&rowsq[wr + 8 + lr], s1); }
    __syncthreads();

    const int r0 = wr + lr, r1 = wr + 8 + lr;
    float rms0 = rsqrtf(rowsq[r0] * (1.0f / CC) + 1e-6f);
    float rms1 = rsqrtf(rowsq[r1] * (1.0f / CC) + 1e-6f);

    const int m0r = m0 + r0, m1r = m0 + r1;
    const int t0 = m0r & 63, b0_ = m0r >> 6, n_0 = b0_ / 25, j0 = b0_ - n_0 * 25;
    const int t1 = m1r & 63, b1_ = m1r >> 6, n_1 = b1_ / 25, j1 = b1_ - n_1 * 25;
    const size_t g0 = ((size_t)(n_0 * TT + t0) * JJ + j0) * CC;
    const size_t g1 = ((size_t)(n_1 * TT + t1) * JJ + j1) * CC;
    #pragma unroll
    for (int jj = 0; jj < 8; jj++) {
        const int col = wc + 8*jj + 2*lk;
        float2 lw = *(const float2*)&ln_w[col];
        float2 x0 = *(const float2*)&x[g0 + col];
        float2 x1 = *(const float2*)&x[g1 + col];
        *(float2*)&out[g0 + col] = make_float2(fmaf(acc[jj][0]*rms0, lw.x, x0.x),
                                               fmaf(acc[jj][1]*rms0, lw.y, x0.y));
        *(float2*)&out[g1 + col] = make_float2(fmaf(acc[jj][2]*rms1, lw.x, x1.x),
                                               fmaf(acc[jj][3]*rms1, lw.y, x1.y));
    }
}

// ---------------- launch ----------------
extern "C" void kernel_launch(void* const* d_in, const int* in_sizes, int n_in,
                              void* d_out, int out_size) {
    const float* x      = (const float*)d_in[0];
    const float* W_in   = (const float*)d_in[1];
    const float* conv_w = (const float*)d_in[2];
    const float* conv_b = (const float*)d_in[3];
    const float* W_xprj = (const float*)d_in[4];
    const float* W_dt   = (const float*)d_in[5];
    const float* b_dt   = (const float*)d_in[6];
    const float* A_log  = (const float*)d_in[7];
    const float* D_skip = (const float*)d_in[8];
    const float* W_out  = (const float*)d_in[9];
    const float* ln_w   = (const float*)d_in[10];
    float* out = (float*)d_out;

    uint32_t* xt; cudaGetSymbolAddress((void**)&xt, g_xt);
    uint32_t* wt; cudaGetSymbolAddress((void**)&wt, g_wt);

    cudaFuncSetAttribute(k1_gemm_in, cudaFuncAttributeMaxDynamicSharedMemorySize, 55296);

    k0_cvt<<<XELEMS / 1024, 256>>>((const float4*)x,    (uint4*)xt, XELEMS / 4);
    k0_cvt<<<WELEMS / 1024, 256>>>((const float4*)W_in, (uint4*)wt, WELEMS / 4);

    k1_gemm_in<<<dim3(BTOT, 8), 256, 55296>>>();
    k2_conv<<<(NROWS * DI) / 256, 256>>>(conv_w, conv_b);
    k3_xproj<<<BTOT, 256>>>(W_xprj, W_dt, b_dt);
    k4_scan<<<dim3(BTOT, 4), 128>>>(A_log, D_skip);
    k5_gemm_out<<<NROWS / 32, 256>>>(x, W_out, ln_w, out);
}